// round 1
// baseline (speedup 1.0000x reference)
#include <cuda_runtime.h>
#include <cuda_bf16.h>

// SoftPool2d: x (16, 96, 256, 256) f32, 2x2 window, stride 2, no pad.
// out (16, 96, 128, 128) f32.
// out[b,c,ho,wo] = sum_i t_i * softmax(t)_i over the 4 taps of each window.
//
// Streaming, non-overlapping windows: read 402.7MB, write 100.7MB -> HBM-bound.
// One thread = 2 output pixels: 2x float4 loads (two input rows), 1x float2 store.

#define B 16
#define C 96
#define H 256
#define W 256
#define HO 128
#define WO 128

// pairs of output pixels: (B*C) * HO * (WO/2) = 1536 * 128 * 64
#define NPAIR (16 * 96 * 128 * 64)

__device__ __forceinline__ float softpool4(float t0, float t1, float t2, float t3) {
    float m = fmaxf(fmaxf(t0, t1), fmaxf(t2, t3));
    float e0 = __expf(t0 - m);
    float e1 = __expf(t1 - m);
    float e2 = __expf(t2 - m);
    float e3 = __expf(t3 - m);
    float num = fmaf(t0, e0, fmaf(t1, e1, fmaf(t2, e2, t3 * e3)));
    float den = e0 + e1 + e2 + e3;
    return num / den;
}

__global__ __launch_bounds__(256) void SoftPool2d_850403524762_kernel(
    const float* __restrict__ x, float* __restrict__ out) {
    int idx = blockIdx.x * blockDim.x + threadIdx.x;
    if (idx >= NPAIR) return;

    int wg = idx & 63;          // which float4 group along W (64 groups of 4 cols)
    int ho = (idx >> 6) & 127;  // output row
    int bc = idx >> 13;         // fused batch*channel plane

    // input rows 2*ho and 2*ho+1 of plane bc
    const float4* r0 = (const float4*)(x + (size_t)bc * (H * W) + (size_t)(2 * ho) * W);
    const float4* r1 = r0 + (W / 4);

    float4 a = __ldg(&r0[wg]);
    float4 b = __ldg(&r1[wg]);

    float2 o;
    o.x = softpool4(a.x, a.y, b.x, b.y);
    o.y = softpool4(a.z, a.w, b.z, b.w);

    float2* orow = (float2*)(out + (size_t)bc * (HO * WO) + (size_t)ho * WO);
    orow[wg] = o;
}

extern "C" void kernel_launch(void* const* d_in, const int* in_sizes, int n_in,
                              void* d_out, int out_size) {
    const float* x = (const float*)d_in[0];
    float* out = (float*)d_out;
    const int threads = 256;
    const int blocks = (NPAIR + threads - 1) / threads;  // 49152
    SoftPool2d_850403524762_kernel<<<blocks, threads>>>(x, out);
}

// round 3
// speedup vs baseline: 1.0351x; 1.0351x over previous
#include <cuda_runtime.h>
#include <cuda_bf16.h>

// SoftPool2d: x (16, 96, 256, 256) f32, 2x2 window, stride 2, no pad.
// out (16, 96, 128, 128) f32.
//
// Pure streaming (no reuse): read 402.7MB + write 100.7MB -> HBM-bound.
// R2: 4 outputs/thread. Each thread loads 2x float4 from each of the 2 input
// rows (4 front-batched LDG.128 -> MLP_p1=4), computes 4 windows, stores one
// float4. Streaming cache hints (ldcs/stcs) since every byte is touched once.

#define H 256
#define W 256
#define HO 128
#define WO 128

// quads of output pixels: (B*C) * HO * (WO/4) = 1536 * 128 * 32
#define NQUAD (16 * 96 * 128 * 32)

__device__ __forceinline__ float softpool4(float t0, float t1, float t2, float t3) {
    float m = fmaxf(fmaxf(t0, t1), fmaxf(t2, t3));
    float e0 = __expf(t0 - m);
    float e1 = __expf(t1 - m);
    float e2 = __expf(t2 - m);
    float e3 = __expf(t3 - m);
    float num = fmaf(t0, e0, fmaf(t1, e1, fmaf(t2, e2, t3 * e3)));
    float den = e0 + e1 + e2 + e3;
    return num * __fdividef(1.0f, den);
}

__global__ __launch_bounds__(256) void SoftPool2d_850403524762_kernel(
    const float* __restrict__ x, float* __restrict__ out) {
    int idx = blockIdx.x * blockDim.x + threadIdx.x;
    if (idx >= NQUAD) return;

    int wg = idx & 31;          // which 8-col group along W (32 groups)
    int ho = (idx >> 5) & 127;  // output row
    int bc = idx >> 12;         // fused batch*channel plane

    // input rows 2*ho and 2*ho+1 of plane bc; 8 input cols -> 2 float4 per row
    const float4* r0 = (const float4*)(x + (size_t)bc * (H * W) + (size_t)(2 * ho) * W) + 2 * wg;
    const float4* r1 = r0 + (W / 4);

    // 4 independent streaming loads, front-batched
    float4 a0 = __ldcs(r0 + 0);
    float4 a1 = __ldcs(r0 + 1);
    float4 b0 = __ldcs(r1 + 0);
    float4 b1 = __ldcs(r1 + 1);

    float4 o;
    o.x = softpool4(a0.x, a0.y, b0.x, b0.y);
    o.y = softpool4(a0.z, a0.w, b0.z, b0.w);
    o.z = softpool4(a1.x, a1.y, b1.x, b1.y);
    o.w = softpool4(a1.z, a1.w, b1.z, b1.w);

    float4* orow = (float4*)(out + (size_t)bc * (HO * WO) + (size_t)ho * WO) + wg;
    __stcs(orow, o);
}

extern "C" void kernel_launch(void* const* d_in, const int* in_sizes, int n_in,
                              void* d_out, int out_size) {
    const float* x = (const float*)d_in[0];
    float* out = (float*)d_out;
    const int threads = 256;
    const int blocks = (NQUAD + threads - 1) / threads;  // 24576
    SoftPool2d_850403524762_kernel<<<blocks, threads>>>(x, out);
}